// round 15
// baseline (speedup 1.0000x reference)
#include <cuda_runtime.h>
#include <cuda_fp16.h>
#include <math.h>
#include <stdint.h>

#define BB 2
#define SS 2048
#define HH 1024
#define NH 16
#define HD 64
#define BS (BB*SS)   // 4096
#define BH (BB*NH)   // 32

// Scratch (allocation-free: static device globals)
__device__ __half d_q[(size_t)BS*HH];
__device__ __half d_k[(size_t)BS*HH];
__device__ __half d_vt[(size_t)HH*BS];     // V transposed: [d][token]
__device__ __half d_x[(size_t)BS*HH];      // fp16 X
__device__ __half d_w[(size_t)3*HH*HH];    // fp16 W^T (per z: [n][k])
__device__ float  d_g[BS];
__device__ float  d_p[BS];
__device__ int    d_perm[BS];              // wide-first query order per batch
__device__ float  d_po[(size_t)2*BH*SS*HD];  // split-j partial O (unnormalized)
__device__ float  d_pm[(size_t)2*BH*SS];     // split-j partial max
__device__ float  d_pl[(size_t)2*BH*SS];     // split-j partial sum

// ---------------------------------------------------------------------------
// helpers
// ---------------------------------------------------------------------------
__device__ __forceinline__ void cp16(uint32_t dst, const void* src){
    asm volatile("cp.async.cg.shared.global [%0], [%1], 16;" :: "r"(dst), "l"(src));
}
__device__ __forceinline__ void cp_commit(){ asm volatile("cp.async.commit_group;"); }
template<int N> __device__ __forceinline__ void cp_wait(){
    asm volatile("cp.async.wait_group %0;" :: "n"(N));
}
__device__ __forceinline__ void mma16(float* c, const uint32_t* a, const uint32_t* b){
    asm volatile("mma.sync.aligned.m16n8k16.row.col.f32.f16.f16.f32 "
        "{%0,%1,%2,%3}, {%4,%5,%6,%7}, {%8,%9}, {%0,%1,%2,%3};"
        : "+f"(c[0]),"+f"(c[1]),"+f"(c[2]),"+f"(c[3])
        : "r"(a[0]),"r"(a[1]),"r"(a[2]),"r"(a[3]), "r"(b[0]),"r"(b[1]));
}
__device__ __forceinline__ void ldsm4(uint32_t* d, uint32_t addr){
    asm volatile("ldmatrix.sync.aligned.m8n8.x4.shared.b16 {%0,%1,%2,%3}, [%4];"
        : "=r"(d[0]),"=r"(d[1]),"=r"(d[2]),"=r"(d[3]) : "r"(addr));
}
__device__ __forceinline__ uint32_t packh2(float a, float b){
    __half2 h = __floats2half2_rn(a, b);
    return *reinterpret_cast<uint32_t*>(&h);
}

// ---------------------------------------------------------------------------
// Merged prep: blocks [0,3072) transpose-convert Wq|Wk|Wv to fp16 W^T;
// blocks [3072,7168) run the gate (+fp16 X convert).
// ---------------------------------------------------------------------------
__global__ __launch_bounds__(256) void prep_kernel(
    const float* __restrict__ Wq, const float* __restrict__ Wk,
    const float* __restrict__ Wv, __half* __restrict__ w,
    const float* __restrict__ X, const float* __restrict__ Wg,
    const float* __restrict__ bg,
    float* __restrict__ g, float* __restrict__ p, __half* __restrict__ xh)
{
    __shared__ float ts[32][33];
    __shared__ float red[256];
    const int bid = blockIdx.x;
    const int tid = threadIdx.x;
    if (bid < 3*1024){
        const int z = bid >> 10, rem = bid & 1023;
        const int n0 = (rem & 31)*32, k0 = (rem >> 5)*32;
        const float* W = (z == 0) ? Wq : (z == 1) ? Wk : Wv;
        const int tx = tid & 31, ty = tid >> 5;
        #pragma unroll
        for (int yy = 0; yy < 4; yy++){
            int k = k0 + ty + yy*8;
            ts[ty + yy*8][tx] = W[(size_t)k*HH + n0 + tx];
        }
        __syncthreads();
        #pragma unroll
        for (int yy = 0; yy < 4; yy++){
            int n = n0 + ty + yy*8;
            w[(size_t)z*HH*HH + (size_t)n*HH + k0 + tx] = __float2half_rn(ts[tx][ty + yy*8]);
        }
    } else {
        const int row = bid - 3072;
        float4 xv = *(const float4*)(X + (size_t)row*HH + tid*4);
        float4 wv = *(const float4*)(Wg + tid*4);
        uint2 o = { packh2(xv.x, xv.y), packh2(xv.z, xv.w) };
        *(uint2*)(xh + (size_t)row*HH + tid*4) = o;
        float s = xv.x*wv.x + xv.y*wv.y + xv.z*wv.z + xv.w*wv.w;
        red[tid] = s; __syncthreads();
        for (int off = 128; off > 0; off >>= 1){
            if (tid < off) red[tid] += red[tid+off];
            __syncthreads();
        }
        if (tid == 0){
            float z2 = red[0] + bg[0];
            float gg = 1.f / (1.f + expf(-z2));
            g[row] = gg;
            p[row] = powf((float)(SS-2), 1.f - gg);
        }
    }
}

// ---------------------------------------------------------------------------
// Query ordering: WIDE-FIRST stable counting sort into 4 pi-buckets per batch.
// ---------------------------------------------------------------------------
__global__ __launch_bounds__(256) void order_kernel(const float* __restrict__ p,
                                                    int* __restrict__ perm){
    const int b = blockIdx.x, tid = threadIdx.x;
    const float* pb = p + (size_t)b*SS;
    __shared__ uint8_t bk[SS];
    __shared__ int sc[1024];
    int myc[4] = {0,0,0,0};
    #pragma unroll
    for (int e = 0; e < 8; e++){
        int i = tid*8 + e;
        float pi = pb[i];
        int k = (pi >= 800.f) ? 0 : (pi >= 288.f) ? 1 : (pi >= 96.f) ? 2 : 3;
        bk[i] = (uint8_t)k; myc[k]++;
    }
    #pragma unroll
    for (int k = 0; k < 4; k++) sc[k*256 + tid] = myc[k];
    __syncthreads();
    for (int off = 1; off < 1024; off <<= 1){
        int v[4];
        #pragma unroll
        for (int k = 0; k < 4; k++){
            int idx = k*256 + tid;
            v[k] = (idx >= off) ? sc[idx - off] : 0;
        }
        __syncthreads();
        #pragma unroll
        for (int k = 0; k < 4; k++) sc[k*256 + tid] += v[k];
        __syncthreads();
    }
    int base[4];
    #pragma unroll
    for (int k = 0; k < 4; k++) base[k] = sc[k*256 + tid] - myc[k];
    #pragma unroll
    for (int e = 0; e < 8; e++){
        int i = tid*8 + e;
        int k = bk[i];
        perm[(size_t)b*SS + base[k]++] = i;
    }
}

// ---------------------------------------------------------------------------
// Merged fp16 QKV projection, FAT WARP TILES: CTA 128x256, 8 warps of 64x64.
// smem-traffic per FLOP halves vs 64x32 warps (mn/(m+n): 21 -> 32 FLOP/B).
// BK=64, 3-stage pipeline, one barrier/iter. z: 0->Q, 1->K, 2->V^T.
// ---------------------------------------------------------------------------
#define PSTR 72
#define NSTG 3
#define STG_HALVES ((128+256)*PSTR)   // A then B per stage

__global__ __launch_bounds__(256, 1) void gemm_proj(
    const __half* __restrict__ A, const __half* __restrict__ Wall,
    const float* __restrict__ b0, const float* __restrict__ b1,
    const float* __restrict__ b2,
    __half* __restrict__ C0, __half* __restrict__ C1, __half* __restrict__ Vt)
{
    const int z = blockIdx.z;
    const __half* Bp = Wall + (size_t)z*HH*HH;
    const float* bias = (z == 0) ? b0 : (z == 1) ? b1 : b2;

    extern __shared__ __half smh[];
    const int tid = threadIdx.x, lane = tid & 31, wid = tid >> 5;
    const int wm = wid >> 2, wn = wid & 3;       // 2 x 4 warps, 64x64 each
    const int gq = lane & 3, gr = lane >> 2;

    const int iBase = blockIdx.y * 128;
    const int jBase = blockIdx.x * 256;

    float acc[4][8][4] = {};    // 64x64 per warp

    auto loadTile = [&](int s, int kk){
        __half* As = smh + (size_t)s*STG_HALVES;
        __half* Bs = As + 128*PSTR;
        uint32_t ab = (uint32_t)__cvta_generic_to_shared(As);
        uint32_t bb = (uint32_t)__cvta_generic_to_shared(Bs);
        #pragma unroll
        for (int i = 0; i < 4; i++){          // A: 128 rows x 64
            int f = tid + i*256;
            int r = f >> 3, c8 = (f & 7) * 8;
            cp16(ab + (uint32_t)(r*PSTR + c8)*2u, A + (size_t)(iBase + r)*HH + kk + c8);
        }
        #pragma unroll
        for (int i = 0; i < 8; i++){          // B: 256 rows x 64
            int f = tid + i*256;
            int n = f >> 3, c8 = (f & 7) * 8;
            cp16(bb + (uint32_t)(n*PSTR + c8)*2u, Bp + (size_t)(jBase + n)*HH + kk + c8);
        }
    };

    const int arow = lane & 15;
    const int acol = (lane >> 4) * 8;
    const int brow = lane & 7;
    const int bcol = (lane >> 3) * 8;

    loadTile(0, 0); cp_commit();
    loadTile(1, 64); cp_commit();

    const int nK = HH / 64;   // 16
    for (int kt = 0; kt < nK; kt++){
        const int cur = kt % NSTG;
        if (kt + 1 < nK) cp_wait<1>(); else cp_wait<0>();
        __syncthreads();
        if (kt + 2 < nK){ loadTile((kt + 2) % NSTG, (kt + 2)*64); cp_commit(); }

        uint32_t abase = (uint32_t)__cvta_generic_to_shared(smh + (size_t)cur*STG_HALVES);
        uint32_t bbase = abase + 128*PSTR*2;
        #pragma unroll
        for (int kp = 0; kp < 2; kp++){
            uint32_t bfp[8][4];
            #pragma unroll
            for (int nt = 0; nt < 8; nt++){
                uint32_t addr = bbase +
                    (uint32_t)((wn*64 + nt*8 + brow)*PSTR + kp*32 + bcol)*2u;
                ldsm4(bfp[nt], addr);
            }
            #pragma unroll
            for (int k2 = 0; k2 < 2; k2++){
                uint32_t af[4][4];
                #pragma unroll
                for (int mt = 0; mt < 4; mt++){
                    uint32_t addr = abase +
                        (uint32_t)((wm*64 + mt*16 + arow)*PSTR + kp*32 + k2*16 + acol)*2u;
                    ldsm4(af[mt], addr);
                }
                #pragma unroll
                for (int mt = 0; mt < 4; mt++)
                    #pragma unroll
                    for (int nt = 0; nt < 8; nt++)
                        mma16(acc[mt][nt], af[mt], &bfp[nt][2*k2]);
            }
        }
    }

    // epilogue
    #pragma unroll
    for (int mt = 0; mt < 4; mt++){
        int r0 = iBase + wm*64 + mt*16 + gr;
        int r1 = r0 + 8;
        #pragma unroll
        for (int nt = 0; nt < 8; nt++){
            int c0 = jBase + wn*64 + nt*8 + 2*gq;
            float bb0 = __ldg(bias + c0), bb1 = __ldg(bias + c0 + 1);
            float v0 = acc[mt][nt][0] + bb0, v1 = acc[mt][nt][1] + bb1;
            float v2 = acc[mt][nt][2] + bb0, v3 = acc[mt][nt][3] + bb1;
            if (z == 2){
                Vt[(size_t)c0*BS + r0]     = __float2half_rn(v0);
                Vt[(size_t)(c0+1)*BS + r0] = __float2half_rn(v1);
                Vt[(size_t)c0*BS + r1]     = __float2half_rn(v2);
                Vt[(size_t)(c0+1)*BS + r1] = __float2half_rn(v3);
            } else {
                __half* C = (z == 0) ? C0 : C1;
                uint32_t p0 = packh2(v0, v1), p1 = packh2(v2, v3);
                *(uint32_t*)(C + (size_t)r0*HH + c0) = p0;
                *(uint32_t*)(C + (size_t)r1*HH + c0) = p1;
            }
        }
    }
}

// ---------------------------------------------------------------------------
// Split-KV fused attention (unchanged from R14).
// ---------------------------------------------------------------------------
#define QSTR 72
#define JT   64
#define NJT  (SS/JT)

__device__ __forceinline__ float penexp(float om, float gi, float pi, int i,
                                        float gj, int j, float se){
    float res = om * fmaxf(om - gj, 0.f) + gi * fminf(om + gj, 1.f);
    float scope = fminf(fmaxf(pi + 2.f - fabsf((float)(i - j)), 1e-32f), 1.f);
    float pen = fmaxf(res * scope, 1e-32f);
    return pen * __expf(se);
}

__global__ __launch_bounds__(256, 2) void attn_fused(
    const __half* __restrict__ Q, const __half* __restrict__ Kg,
    const __half* __restrict__ Vt, const float* __restrict__ g,
    const float* __restrict__ p, const int* __restrict__ perm,
    float* __restrict__ po, float* __restrict__ pm, float* __restrict__ pl)
{
    const int bh = blockIdx.x, b = bh >> 4, h = bh & 15;
    const int half = blockIdx.y;
    const int iBase = blockIdx.z * 128;
    const int tid = threadIdx.x, lane = tid & 31, wid = tid >> 5;

    extern __shared__ __half smh[];
    __half* Qs  = smh;
    __half* Ks0 = Qs  + 128*QSTR;
    __half* Vs0 = Ks0 + 2*JT*QSTR;
    float*  gs  = (float*)(Vs0 + 2*JT*QSTR);
    __shared__ int bandLo[8], bandHi[8];

    const __half* Qp = Q  + (size_t)b*SS*HH + h*HD;
    const __half* Kp = Kg + (size_t)b*SS*HH + h*HD;
    const int* pmr = perm + (size_t)b*SS;

    {
        uint32_t qb = (uint32_t)__cvta_generic_to_shared(Qs);
        #pragma unroll
        for (int l = 0; l < 4; l++){
            int f = tid + l*256;
            int r = f >> 3, c8 = (f & 7) * 8;
            int pr = __ldg(pmr + iBase + r);
            cp16(qb + (uint32_t)(r*QSTR + c8)*2u, Qp + (size_t)pr*HH + c8);
        }
        uint32_t gb = (uint32_t)__cvta_generic_to_shared(gs);
        #pragma unroll
        for (int l = 0; l < 2; l++){
            int f = tid + l*256;
            cp16(gb + (uint32_t)f*16u, g + (size_t)b*SS + f*4);
        }
        cp_commit();
    }
    auto loadK = [&](int s, int j0){
        uint32_t kb = (uint32_t)__cvta_generic_to_shared(Ks0 + s*JT*QSTR);
        #pragma unroll
        for (int l = 0; l < 2; l++){
            int f = tid + l*256;
            int r = f >> 3, c8 = (f & 7) * 8;
            cp16(kb + (uint32_t)(r*QSTR + c8)*2u, Kp + (size_t)(j0 + r)*HH + c8);
        }
    };
    auto loadV = [&](int s, int j0){
        uint32_t vb = (uint32_t)__cvta_generic_to_shared(Vs0 + s*JT*QSTR);
        #pragma unroll
        for (int l = 0; l < 2; l++){
            int f = tid + l*256;
            int d = f >> 3, c8 = (f & 7) * 8;
            cp16(vb + (uint32_t)(d*QSTR + c8)*2u,
                 Vt + (size_t)(h*HD + d)*BS + b*SS + j0 + c8);
        }
    };

    const int gq = lane & 3, gr = lane >> 2;
    const int lr0 = wid*16 + gr;
    const int lr1 = lr0 + 8;
    const int ri0 = __ldg(pmr + iBase + lr0);
    const int ri1 = __ldg(pmr + iBase + lr1);
    const float gi0 = __ldg(g + (size_t)b*SS + ri0);
    const float gi1 = __ldg(g + (size_t)b*SS + ri1);
    const float pi0 = __ldg(p + (size_t)b*SS + ri0);
    const float pi1 = __ldg(p + (size_t)b*SS + ri1);
    const float om0 = 1.f - gi0, om1 = 1.f - gi1;

    float wlo = fminf((float)ri0 - pi0, (float)ri1 - pi1);
    float whi = fmaxf((float)ri0 + pi0, (float)ri1 + pi1);
    #pragma unroll
    for (int off = 16; off > 0; off >>= 1){
        wlo = fminf(wlo, __shfl_xor_sync(0xffffffffu, wlo, off));
        whi = fmaxf(whi, __shfl_xor_sync(0xffffffffu, whi, off));
    }
    const int blo = (int)floorf(wlo) - 3;
    const int bhi = (int)ceilf(whi) + 3;

    if (lane == 0){ bandLo[wid] = blo; bandHi[wid] = bhi; }
    __syncthreads();
    int cLo = bandLo[0], cHi = bandHi[0];
    #pragma unroll
    for (int wI = 1; wI < 8; wI++){
        cLo = min(cLo, bandLo[wI]); cHi = max(cHi, bandHi[wI]);
    }
    const int jtLo = (cLo <= 0) ? 0 : min(NJT-1, cLo / JT);
    const int jtHi = min(NJT-1, max(0, cHi) / JT);
    const int nTiles = jtHi - jtLo + 1;
    const int jtMid = jtLo + (nTiles + 1) / 2;
    const int myLo  = (half == 0) ? jtLo  : jtMid;
    const int myEnd = (half == 0) ? jtMid : jtHi + 1;

    float m0 = -1e30f, m1 = -1e30f, l0 = 0.f, l1 = 0.f;
    float oacc[8][4] = {};

    if (myLo < myEnd){
        loadK(0, myLo*JT); loadV(0, myLo*JT); cp_commit();

        for (int jt = myLo; jt < myEnd; jt++){
            const int cur = (jt - myLo) & 1;
            if (jt + 1 < myEnd){
                loadK(cur ^ 1, (jt+1)*JT); loadV(cur ^ 1, (jt+1)*JT);
                cp_commit(); cp_wait<1>();
            } else {
                cp_wait<0>();
            }
            __syncthreads();
            const int jBase = jt*JT;
            const bool active = (jBase + JT - 1 >= blo) && (jBase <= bhi);
            if (active){
                const __half* Ks = Ks0 + cur*JT*QSTR;
                const __half* Vs = Vs0 + cur*JT*QSTR;

                float sacc[8][4];
                #pragma unroll
                for (int nt = 0; nt < 8; nt++){
                    sacc[nt][0]=0.f; sacc[nt][1]=0.f; sacc[nt][2]=0.f; sacc[nt][3]=0.f;
                }
                #pragma unroll
                for (int ks = 0; ks < 4; ks++){
                    const int k0 = ks*16 + 2*gq;
                    uint32_t af[4];
                    af[0] = *(const uint32_t*)&Qs[lr0*QSTR + k0];
                    af[1] = *(const uint32_t*)&Qs[lr1*QSTR + k0];
                    af[2] = *(const uint32_t*)&Qs[lr0*QSTR + k0 + 8];
                    af[3] = *(const uint32_t*)&Qs[lr1*QSTR + k0 + 8];
                    #pragma unroll
                    for (int nt = 0; nt < 8; nt++){
                        const int n = nt*8 + gr;
                        uint32_t bf[2];
                        bf[0] = *(const uint32_t*)&Ks[n*QSTR + k0];
                        bf[1] = *(const uint32_t*)&Ks[n*QSTR + k0 + 8];
                        mma16(sacc[nt], af, bf);
                    }
                }

                float tm0 = -1e30f, tm1 = -1e30f;
                #pragma unroll
                for (int nt = 0; nt < 8; nt++){
                    tm0 = fmaxf(tm0, fmaxf(sacc[nt][0], sacc[nt][1]));
                    tm1 = fmaxf(tm1, fmaxf(sacc[nt][2], sacc[nt][3]));
                }
                tm0 = fmaxf(tm0, __shfl_xor_sync(0xffffffffu, tm0, 1));
                tm0 = fmaxf(tm0, __shfl_xor_sync(0xffffffffu, tm0, 2));
                tm1 = fmaxf(tm1, __shfl_xor_sync(0xffffffffu, tm1, 1));
                tm1 = fmaxf(tm1, __shfl_xor_sync(0xffffffffu, tm1, 2));
                tm0 *= 0.125f; tm1 *= 0.125f;
                const float m0n = fmaxf(m0, tm0), m1n = fmaxf(m1, tm1);
                const float f0 = __expf(m0 - m0n), f1 = __expf(m1 - m1n);
                m0 = m0n; m1 = m1n;
                l0 *= f0; l1 *= f1;
                #pragma unroll
                for (int dn = 0; dn < 8; dn++){
                    oacc[dn][0] *= f0; oacc[dn][1] *= f0;
                    oacc[dn][2] *= f1; oacc[dn][3] *= f1;
                }
                float rs0 = 0.f, rs1 = 0.f;
                #pragma unroll
                for (int nt = 0; nt < 8; nt++){
                    const int j0 = jBase + nt*8 + 2*gq;
                    const int j1 = j0 + 1;
                    const float gj0 = gs[j0], gj1 = gs[j1];
                    float t00 = penexp(om0, gi0, pi0, ri0, gj0, j0, sacc[nt][0]*0.125f - m0);
                    float t01 = penexp(om0, gi0, pi0, ri0, gj1, j1, sacc[nt][1]*0.125f - m0);
                    float t10 = penexp(om1, gi1, pi1, ri1, gj0, j0, sacc[nt][2]*0.125f - m1);
                    float t11 = penexp(om1, gi1, pi1, ri1, gj1, j1, sacc[nt][3]*0.125f - m1);
                    sacc[nt][0] = t00; sacc[nt][1] = t01;
                    sacc[nt][2] = t10; sacc[nt][3] = t11;
                    rs0 += t00 + t01; rs1 += t10 + t11;
                }
                rs0 += __shfl_xor_sync(0xffffffffu, rs0, 1);
                rs0 += __shfl_xor_sync(0xffffffffu, rs0, 2);
                rs1 += __shfl_xor_sync(0xffffffffu, rs1, 1);
                rs1 += __shfl_xor_sync(0xffffffffu, rs1, 2);
                l0 += rs0; l1 += rs1;

                #pragma unroll
                for (int kc = 0; kc < 4; kc++){
                    uint32_t af[4];
                    af[0] = packh2(sacc[2*kc][0],   sacc[2*kc][1]);
                    af[1] = packh2(sacc[2*kc][2],   sacc[2*kc][3]);
                    af[2] = packh2(sacc[2*kc+1][0], sacc[2*kc+1][1]);
                    af[3] = packh2(sacc[2*kc+1][2], sacc[2*kc+1][3]);
                    const int kb = kc*16 + 2*gq;
                    #pragma unroll
                    for (int dn = 0; dn < 8; dn++){
                        const int d0 = dn*8 + gr;
                        uint32_t bf[2];
                        bf[0] = *(const uint32_t*)&Vs[d0*QSTR + kb];
                        bf[1] = *(const uint32_t*)&Vs[d0*QSTR + kb + 8];
                        mma16(oacc[dn], af, bf);
                    }
                }
            }
            __syncthreads();
        }
    } else {
        cp_wait<0>();
    }

    const size_t base = (size_t)(half*BH + bh)*SS;
    #pragma unroll
    for (int dn = 0; dn < 8; dn++){
        const int c0 = dn*8 + 2*gq;
        *(float2*)(po + (base + ri0)*HD + c0) = make_float2(oacc[dn][0], oacc[dn][1]);
        *(float2*)(po + (base + ri1)*HD + c0) = make_float2(oacc[dn][2], oacc[dn][3]);
    }
    if (gq == 0){
        pm[base + ri0] = m0; pl[base + ri0] = l0;
        pm[base + ri1] = m1; pl[base + ri1] = l1;
    }
}

// ---------------------------------------------------------------------------
// Combine halves.
// ---------------------------------------------------------------------------
__global__ __launch_bounds__(256) void combine_kernel(
    const float* __restrict__ po, const float* __restrict__ pm,
    const float* __restrict__ pl, float* __restrict__ out)
{
    const int idx = blockIdx.x*8 + (threadIdx.x >> 5);
    const int lane = threadIdx.x & 31;
    const int bh = idx >> 11, i = idx & (SS - 1);
    const int b = bh >> 4, h = bh & 15;
    const float m0 = pm[idx],            m1 = pm[BH*SS + idx];
    const float l0 = pl[idx],            l1 = pl[BH*SS + idx];
    const float M  = fmaxf(m0, m1);
    const float w0 = __expf(m0 - M), w1 = __expf(m1 - M);
    const float inv = 1.f / fmaxf(w0*l0 + w1*l1, 1e-37f);
    float2 a = *(const float2*)(po + (size_t)idx*HD + lane*2);
    float2 c = *(const float2*)(po + (size_t)(BH*SS + idx)*HD + lane*2);
    float* op = out + ((size_t)b*SS + i)*HH + h*HD + lane*2;
    float2 r = { (w0*a.x + w1*c.x)*inv, (w0*a.y + w1*c.y)*inv };
    *(float2*)op = r;
}

// ---------------------------------------------------------------------------
extern "C" void kernel_launch(void* const* d_in, const int* in_sizes, int n_in,
                              void* d_out, int out_size) {
    const float* X  = (const float*)d_in[0];
    const float* Wq = (const float*)d_in[1];
    const float* bq = (const float*)d_in[2];
    const float* Wk = (const float*)d_in[3];
    const float* bk = (const float*)d_in[4];
    const float* Wv = (const float*)d_in[5];
    const float* bv = (const float*)d_in[6];
    const float* Wg = (const float*)d_in[7];
    const float* bg = (const float*)d_in[8];
    float* out = (float*)d_out;

    __half *q, *k, *vt, *x, *w;
    float *g, *p, *po, *pmb, *plb;
    int *perm;
    cudaGetSymbolAddress((void**)&q,  d_q);
    cudaGetSymbolAddress((void**)&k,  d_k);
    cudaGetSymbolAddress((void**)&vt, d_vt);
    cudaGetSymbolAddress((void**)&x,  d_x);
    cudaGetSymbolAddress((void**)&w,  d_w);
    cudaGetSymbolAddress((void**)&g,  d_g);
    cudaGetSymbolAddress((void**)&p,  d_p);
    cudaGetSymbolAddress((void**)&perm, d_perm);
    cudaGetSymbolAddress((void**)&po,  d_po);
    cudaGetSymbolAddress((void**)&pmb, d_pm);
    cudaGetSymbolAddress((void**)&plb, d_pl);

    constexpr int SM_PROJ = NSTG*STG_HALVES*2;                               // 165888
    constexpr int SM_ATTN = (128*QSTR + 2*JT*QSTR + 2*JT*QSTR)*2 + SS*4;     // 63488
    cudaFuncSetAttribute(gemm_proj,
                         cudaFuncAttributeMaxDynamicSharedMemorySize, SM_PROJ);
    cudaFuncSetAttribute(attn_fused,
                         cudaFuncAttributeMaxDynamicSharedMemorySize, SM_ATTN);

    // merged prep (tconv + gate), then ordering
    prep_kernel<<<3*1024 + BS, 256>>>(Wq, Wk, Wv, w, X, Wg, bg, g, p, x);
    order_kernel<<<BB, 256>>>(p, perm);

    // fat-tile QKV projection: CTA 128x256
    dim3 gp(HH/256, BS/128, 3);   // (4, 32, 3)
    gemm_proj<<<gp, 256, SM_PROJ>>>(x, w, bq, bk, bv, q, k, vt);

    // split-KV attn
    dim3 ga(BH, 2, SS/128);       // (32, 2, 16)
    attn_fused<<<ga, 256, SM_ATTN>>>(q, k, vt, g, p, perm, po, pmb, plb);

    // merge halves
    combine_kernel<<<BH*SS/8, 256>>>(po, pmb, plb, out);
}

// round 16
// speedup vs baseline: 1.0312x; 1.0312x over previous
#include <cuda_runtime.h>
#include <cuda_fp16.h>
#include <math.h>
#include <stdint.h>

#define BB 2
#define SS 2048
#define HH 1024
#define NH 16
#define HD 64
#define BS (BB*SS)   // 4096
#define BH (BB*NH)   // 32

// Scratch (allocation-free: static device globals)
__device__ __half d_q[(size_t)BS*HH];      // Q pre-scaled by 0.125
__device__ __half d_k[(size_t)BS*HH];
__device__ __half d_vt[(size_t)HH*BS];     // V transposed: [d][token]
__device__ __half d_x[(size_t)BS*HH];      // fp16 X
__device__ __half d_w[(size_t)3*HH*HH];    // fp16 W^T (per z: [n][k])
__device__ float  d_g[BS];
__device__ float  d_p[BS];
__device__ int    d_perm[BS];              // wide-first query order per batch

// ---------------------------------------------------------------------------
// helpers
// ---------------------------------------------------------------------------
__device__ __forceinline__ void cp16(uint32_t dst, const void* src){
    asm volatile("cp.async.cg.shared.global [%0], [%1], 16;" :: "r"(dst), "l"(src));
}
__device__ __forceinline__ void cp_commit(){ asm volatile("cp.async.commit_group;"); }
template<int N> __device__ __forceinline__ void cp_wait(){
    asm volatile("cp.async.wait_group %0;" :: "n"(N));
}
__device__ __forceinline__ void mma16(float* c, const uint32_t* a, const uint32_t* b){
    asm volatile("mma.sync.aligned.m16n8k16.row.col.f32.f16.f16.f32 "
        "{%0,%1,%2,%3}, {%4,%5,%6,%7}, {%8,%9}, {%0,%1,%2,%3};"
        : "+f"(c[0]),"+f"(c[1]),"+f"(c[2]),"+f"(c[3])
        : "r"(a[0]),"r"(a[1]),"r"(a[2]),"r"(a[3]), "r"(b[0]),"r"(b[1]));
}
__device__ __forceinline__ void ldsm4(uint32_t* d, uint32_t addr){
    asm volatile("ldmatrix.sync.aligned.m8n8.x4.shared.b16 {%0,%1,%2,%3}, [%4];"
        : "=r"(d[0]),"=r"(d[1]),"=r"(d[2]),"=r"(d[3]) : "r"(addr));
}
__device__ __forceinline__ uint32_t packh2(float a, float b){
    __half2 h = __floats2half2_rn(a, b);
    return *reinterpret_cast<uint32_t*>(&h);
}

// ---------------------------------------------------------------------------
// Merged prep: blocks [0,3072) transpose-convert Wq|Wk|Wv to fp16 W^T;
// blocks [3072,7168) run the gate (+fp16 X convert).
// ---------------------------------------------------------------------------
__global__ __launch_bounds__(256) void prep_kernel(
    const float* __restrict__ Wq, const float* __restrict__ Wk,
    const float* __restrict__ Wv, __half* __restrict__ w,
    const float* __restrict__ X, const float* __restrict__ Wg,
    const float* __restrict__ bg,
    float* __restrict__ g, float* __restrict__ p, __half* __restrict__ xh)
{
    __shared__ float ts[32][33];
    __shared__ float red[256];
    const int bid = blockIdx.x;
    const int tid = threadIdx.x;
    if (bid < 3*1024){
        const int z = bid >> 10, rem = bid & 1023;
        const int n0 = (rem & 31)*32, k0 = (rem >> 5)*32;
        const float* W = (z == 0) ? Wq : (z == 1) ? Wk : Wv;
        const int tx = tid & 31, ty = tid >> 5;
        #pragma unroll
        for (int yy = 0; yy < 4; yy++){
            int k = k0 + ty + yy*8;
            ts[ty + yy*8][tx] = W[(size_t)k*HH + n0 + tx];
        }
        __syncthreads();
        #pragma unroll
        for (int yy = 0; yy < 4; yy++){
            int n = n0 + ty + yy*8;
            w[(size_t)z*HH*HH + (size_t)n*HH + k0 + tx] = __float2half_rn(ts[tx][ty + yy*8]);
        }
    } else {
        const int row = bid - 3072;
        float4 xv = *(const float4*)(X + (size_t)row*HH + tid*4);
        float4 wv = *(const float4*)(Wg + tid*4);
        uint2 o = { packh2(xv.x, xv.y), packh2(xv.z, xv.w) };
        *(uint2*)(xh + (size_t)row*HH + tid*4) = o;
        float s = xv.x*wv.x + xv.y*wv.y + xv.z*wv.z + xv.w*wv.w;
        red[tid] = s; __syncthreads();
        for (int off = 128; off > 0; off >>= 1){
            if (tid < off) red[tid] += red[tid+off];
            __syncthreads();
        }
        if (tid == 0){
            float z2 = red[0] + bg[0];
            float gg = 1.f / (1.f + expf(-z2));
            g[row] = gg;
            p[row] = powf((float)(SS-2), 1.f - gg);
        }
    }
}

// ---------------------------------------------------------------------------
// Query ordering: WIDE-FIRST stable counting sort into 4 pi-buckets per batch.
// ---------------------------------------------------------------------------
__global__ __launch_bounds__(256) void order_kernel(const float* __restrict__ p,
                                                    int* __restrict__ perm){
    const int b = blockIdx.x, tid = threadIdx.x;
    const float* pb = p + (size_t)b*SS;
    __shared__ uint8_t bk[SS];
    __shared__ int sc[1024];
    int myc[4] = {0,0,0,0};
    #pragma unroll
    for (int e = 0; e < 8; e++){
        int i = tid*8 + e;
        float pi = pb[i];
        int k = (pi >= 800.f) ? 0 : (pi >= 288.f) ? 1 : (pi >= 96.f) ? 2 : 3;
        bk[i] = (uint8_t)k; myc[k]++;
    }
    #pragma unroll
    for (int k = 0; k < 4; k++) sc[k*256 + tid] = myc[k];
    __syncthreads();
    for (int off = 1; off < 1024; off <<= 1){
        int v[4];
        #pragma unroll
        for (int k = 0; k < 4; k++){
            int idx = k*256 + tid;
            v[k] = (idx >= off) ? sc[idx - off] : 0;
        }
        __syncthreads();
        #pragma unroll
        for (int k = 0; k < 4; k++) sc[k*256 + tid] += v[k];
        __syncthreads();
    }
    int base[4];
    #pragma unroll
    for (int k = 0; k < 4; k++) base[k] = sc[k*256 + tid] - myc[k];
    #pragma unroll
    for (int e = 0; e < 8; e++){
        int i = tid*8 + e;
        int k = bk[i];
        perm[(size_t)b*SS + base[k]++] = i;
    }
}

// ---------------------------------------------------------------------------
// Merged fp16 QKV projection: ldmatrix, BK=64, 3-stage pipeline (R13 config).
// z: 0->Q (scaled by 0.125), 1->K, 2->V^T.
// ---------------------------------------------------------------------------
#define PSTR 72
#define NSTG 3

__global__ __launch_bounds__(256, 2) void gemm_proj(
    const __half* __restrict__ A, const __half* __restrict__ Wall,
    const float* __restrict__ b0, const float* __restrict__ b1,
    const float* __restrict__ b2,
    __half* __restrict__ C0, __half* __restrict__ C1, __half* __restrict__ Vt)
{
    const int z = blockIdx.z;
    const __half* Bp = Wall + (size_t)z*HH*HH;
    const float* bias = (z == 0) ? b0 : (z == 1) ? b1 : b2;

    extern __shared__ __half smh[];
    const int tid = threadIdx.x, lane = tid & 31, wid = tid >> 5;
    const int wm = wid >> 2, wn = wid & 3;
    const int gq = lane & 3, gr = lane >> 2;

    const int iBase = blockIdx.y * 128;
    const int jBase = blockIdx.x * 128;

    float acc[4][4][4] = {};

    auto loadTile = [&](int s, int kk){
        __half* As = smh + (size_t)s*2*128*PSTR;
        __half* Bs = As + 128*PSTR;
        uint32_t ab = (uint32_t)__cvta_generic_to_shared(As);
        uint32_t bb = (uint32_t)__cvta_generic_to_shared(Bs);
        #pragma unroll
        for (int i = 0; i < 4; i++){
            int f = tid + i*256;
            int r = f >> 3, c8 = (f & 7) * 8;
            cp16(ab + (uint32_t)(r*PSTR + c8)*2u, A + (size_t)(iBase + r)*HH + kk + c8);
        }
        #pragma unroll
        for (int i = 0; i < 4; i++){
            int f = tid + i*256;
            int n = f >> 3, c8 = (f & 7) * 8;
            cp16(bb + (uint32_t)(n*PSTR + c8)*2u, Bp + (size_t)(jBase + n)*HH + kk + c8);
        }
    };

    const int arow = lane & 15;
    const int acol = (lane >> 4) * 8;
    const int brow = lane & 7;
    const int bcol = (lane >> 3) * 8;

    loadTile(0, 0); cp_commit();
    loadTile(1, 64); cp_commit();

    const int nK = HH / 64;
    for (int kt = 0; kt < nK; kt++){
        const int cur = kt % NSTG;
        if (kt + 1 < nK) cp_wait<1>(); else cp_wait<0>();
        __syncthreads();
        if (kt + 2 < nK){ loadTile((kt + 2) % NSTG, (kt + 2)*64); cp_commit(); }

        uint32_t abase = (uint32_t)__cvta_generic_to_shared(smh + (size_t)cur*2*128*PSTR);
        uint32_t bbase = abase + 128*PSTR*2;
        #pragma unroll
        for (int kp = 0; kp < 2; kp++){
            uint32_t bfp[4][4];
            #pragma unroll
            for (int nt = 0; nt < 4; nt++){
                uint32_t addr = bbase +
                    (uint32_t)((wn*32 + nt*8 + brow)*PSTR + kp*32 + bcol)*2u;
                ldsm4(bfp[nt], addr);
            }
            #pragma unroll
            for (int k2 = 0; k2 < 2; k2++){
                uint32_t af[4][4];
                #pragma unroll
                for (int mt = 0; mt < 4; mt++){
                    uint32_t addr = abase +
                        (uint32_t)((wm*64 + mt*16 + arow)*PSTR + kp*32 + k2*16 + acol)*2u;
                    ldsm4(af[mt], addr);
                }
                #pragma unroll
                for (int mt = 0; mt < 4; mt++)
                    #pragma unroll
                    for (int nt = 0; nt < 4; nt++)
                        mma16(acc[mt][nt], af[mt], &bfp[nt][2*k2]);
            }
        }
    }

    const float oscale = (z == 0) ? 0.125f : 1.0f;   // fold softmax scale into Q
    #pragma unroll
    for (int mt = 0; mt < 4; mt++){
        int r0 = iBase + wm*64 + mt*16 + gr;
        int r1 = r0 + 8;
        #pragma unroll
        for (int nt = 0; nt < 4; nt++){
            int c0 = jBase + wn*32 + nt*8 + 2*gq;
            float bb0 = __ldg(bias + c0), bb1 = __ldg(bias + c0 + 1);
            float v0 = (acc[mt][nt][0] + bb0)*oscale, v1 = (acc[mt][nt][1] + bb1)*oscale;
            float v2 = (acc[mt][nt][2] + bb0)*oscale, v3 = (acc[mt][nt][3] + bb1)*oscale;
            if (z == 2){
                Vt[(size_t)c0*BS + r0]     = __float2half_rn(v0);
                Vt[(size_t)(c0+1)*BS + r0] = __float2half_rn(v1);
                Vt[(size_t)c0*BS + r1]     = __float2half_rn(v2);
                Vt[(size_t)(c0+1)*BS + r1] = __float2half_rn(v3);
            } else {
                __half* C = (z == 0) ? C0 : C1;
                uint32_t p0 = packh2(v0, v1), p1 = packh2(v2, v3);
                *(uint32_t*)(C + (size_t)r0*HH + c0) = p0;
                *(uint32_t*)(C + (size_t)r1*HH + c0) = p1;
            }
        }
    }
}

// ---------------------------------------------------------------------------
// Fused fp16 flash attention (R11/R13 non-split form): wide-first ordering,
// CTA-band j-loop, per-warp skip. Q pre-scaled by 0.125, so S needs no scale.
// Grid (bh, itile): itile-major launch puts wide CTAs first.
// ---------------------------------------------------------------------------
#define QSTR 72
#define JT   64
#define NJT  (SS/JT)

__device__ __forceinline__ float penexp(float om, float gi, float pi, int i,
                                        float gj, int j, float se){
    float res = om * fmaxf(om - gj, 0.f) + gi * fminf(om + gj, 1.f);
    float scope = fminf(fmaxf(pi + 2.f - fabsf((float)(i - j)), 1e-32f), 1.f);
    float pen = fmaxf(res * scope, 1e-32f);
    return pen * __expf(se);
}

__global__ __launch_bounds__(256, 2) void attn_fused(
    const __half* __restrict__ Q, const __half* __restrict__ Kg,
    const __half* __restrict__ Vt, const float* __restrict__ g,
    const float* __restrict__ p, const int* __restrict__ perm,
    float* __restrict__ out)
{
    const int bh = blockIdx.x, b = bh >> 4, h = bh & 15;
    const int iBase = blockIdx.y * 128;
    const int tid = threadIdx.x, lane = tid & 31, wid = tid >> 5;

    extern __shared__ __half smh[];
    __half* Qs  = smh;
    __half* Ks0 = Qs  + 128*QSTR;
    __half* Vs0 = Ks0 + 2*JT*QSTR;
    float*  gs  = (float*)(Vs0 + 2*JT*QSTR);
    __shared__ int bandLo[8], bandHi[8];

    const __half* Qp = Q  + (size_t)b*SS*HH + h*HD;
    const __half* Kp = Kg + (size_t)b*SS*HH + h*HD;
    const int* pm = perm + (size_t)b*SS;

    {
        uint32_t qb = (uint32_t)__cvta_generic_to_shared(Qs);
        #pragma unroll
        for (int l = 0; l < 4; l++){
            int f = tid + l*256;
            int r = f >> 3, c8 = (f & 7) * 8;
            int pr = __ldg(pm + iBase + r);
            cp16(qb + (uint32_t)(r*QSTR + c8)*2u, Qp + (size_t)pr*HH + c8);
        }
        uint32_t gb = (uint32_t)__cvta_generic_to_shared(gs);
        #pragma unroll
        for (int l = 0; l < 2; l++){
            int f = tid + l*256;
            cp16(gb + (uint32_t)f*16u, g + (size_t)b*SS + f*4);
        }
        cp_commit();
    }
    auto loadK = [&](int s, int j0){
        uint32_t kb = (uint32_t)__cvta_generic_to_shared(Ks0 + s*JT*QSTR);
        #pragma unroll
        for (int l = 0; l < 2; l++){
            int f = tid + l*256;
            int r = f >> 3, c8 = (f & 7) * 8;
            cp16(kb + (uint32_t)(r*QSTR + c8)*2u, Kp + (size_t)(j0 + r)*HH + c8);
        }
    };
    auto loadV = [&](int s, int j0){
        uint32_t vb = (uint32_t)__cvta_generic_to_shared(Vs0 + s*JT*QSTR);
        #pragma unroll
        for (int l = 0; l < 2; l++){
            int f = tid + l*256;
            int d = f >> 3, c8 = (f & 7) * 8;
            cp16(vb + (uint32_t)(d*QSTR + c8)*2u,
                 Vt + (size_t)(h*HD + d)*BS + b*SS + j0 + c8);
        }
    };

    const int gq = lane & 3, gr = lane >> 2;
    const int lr0 = wid*16 + gr;
    const int lr1 = lr0 + 8;
    const int ri0 = __ldg(pm + iBase + lr0);
    const int ri1 = __ldg(pm + iBase + lr1);
    const float gi0 = __ldg(g + (size_t)b*SS + ri0);
    const float gi1 = __ldg(g + (size_t)b*SS + ri1);
    const float pi0 = __ldg(p + (size_t)b*SS + ri0);
    const float pi1 = __ldg(p + (size_t)b*SS + ri1);
    const float om0 = 1.f - gi0, om1 = 1.f - gi1;

    float wlo = fminf((float)ri0 - pi0, (float)ri1 - pi1);
    float whi = fmaxf((float)ri0 + pi0, (float)ri1 + pi1);
    #pragma unroll
    for (int off = 16; off > 0; off >>= 1){
        wlo = fminf(wlo, __shfl_xor_sync(0xffffffffu, wlo, off));
        whi = fmaxf(whi, __shfl_xor_sync(0xffffffffu, whi, off));
    }
    const int blo = (int)floorf(wlo) - 3;
    const int bhi = (int)ceilf(whi) + 3;

    if (lane == 0){ bandLo[wid] = blo; bandHi[wid] = bhi; }
    __syncthreads();
    int cLo = bandLo[0], cHi = bandHi[0];
    #pragma unroll
    for (int wI = 1; wI < 8; wI++){
        cLo = min(cLo, bandLo[wI]); cHi = max(cHi, bandHi[wI]);
    }
    const int jtLo = (cLo <= 0) ? 0 : min(NJT-1, cLo / JT);
    const int jtHi = min(NJT-1, max(0, cHi) / JT);

    loadK(0, jtLo*JT); loadV(0, jtLo*JT); cp_commit();

    float m0 = -1e30f, m1 = -1e30f, l0 = 0.f, l1 = 0.f;
    float oacc[8][4] = {};

    for (int jt = jtLo; jt <= jtHi; jt++){
        const int cur = (jt - jtLo) & 1;
        if (jt + 1 <= jtHi){
            loadK(cur ^ 1, (jt+1)*JT); loadV(cur ^ 1, (jt+1)*JT);
            cp_commit(); cp_wait<1>();
        } else {
            cp_wait<0>();
        }
        __syncthreads();
        const int jBase = jt*JT;
        const bool active = (jBase + JT - 1 >= blo) && (jBase <= bhi);
        if (active){
            const __half* Ks = Ks0 + cur*JT*QSTR;
            const __half* Vs = Vs0 + cur*JT*QSTR;

            // --- S = (Q/8) K^T : already scaled ---
            float sacc[8][4];
            #pragma unroll
            for (int nt = 0; nt < 8; nt++){
                sacc[nt][0]=0.f; sacc[nt][1]=0.f; sacc[nt][2]=0.f; sacc[nt][3]=0.f;
            }
            #pragma unroll
            for (int ks = 0; ks < 4; ks++){
                const int k0 = ks*16 + 2*gq;
                uint32_t af[4];
                af[0] = *(const uint32_t*)&Qs[lr0*QSTR + k0];
                af[1] = *(const uint32_t*)&Qs[lr1*QSTR + k0];
                af[2] = *(const uint32_t*)&Qs[lr0*QSTR + k0 + 8];
                af[3] = *(const uint32_t*)&Qs[lr1*QSTR + k0 + 8];
                #pragma unroll
                for (int nt = 0; nt < 8; nt++){
                    const int n = nt*8 + gr;
                    uint32_t bf[2];
                    bf[0] = *(const uint32_t*)&Ks[n*QSTR + k0];
                    bf[1] = *(const uint32_t*)&Ks[n*QSTR + k0 + 8];
                    mma16(sacc[nt], af, bf);
                }
            }

            // --- online softmax (no rescale needed) ---
            float tm0 = -1e30f, tm1 = -1e30f;
            #pragma unroll
            for (int nt = 0; nt < 8; nt++){
                tm0 = fmaxf(tm0, fmaxf(sacc[nt][0], sacc[nt][1]));
                tm1 = fmaxf(tm1, fmaxf(sacc[nt][2], sacc[nt][3]));
            }
            tm0 = fmaxf(tm0, __shfl_xor_sync(0xffffffffu, tm0, 1));
            tm0 = fmaxf(tm0, __shfl_xor_sync(0xffffffffu, tm0, 2));
            tm1 = fmaxf(tm1, __shfl_xor_sync(0xffffffffu, tm1, 1));
            tm1 = fmaxf(tm1, __shfl_xor_sync(0xffffffffu, tm1, 2));
            const float m0n = fmaxf(m0, tm0), m1n = fmaxf(m1, tm1);
            const float f0 = __expf(m0 - m0n), f1 = __expf(m1 - m1n);
            m0 = m0n; m1 = m1n;
            l0 *= f0; l1 *= f1;
            #pragma unroll
            for (int dn = 0; dn < 8; dn++){
                oacc[dn][0] *= f0; oacc[dn][1] *= f0;
                oacc[dn][2] *= f1; oacc[dn][3] *= f1;
            }
            float rs0 = 0.f, rs1 = 0.f;
            #pragma unroll
            for (int nt = 0; nt < 8; nt++){
                const int j0 = jBase + nt*8 + 2*gq;
                const int j1 = j0 + 1;
                const float gj0 = gs[j0], gj1 = gs[j1];
                float t00 = penexp(om0, gi0, pi0, ri0, gj0, j0, sacc[nt][0] - m0);
                float t01 = penexp(om0, gi0, pi0, ri0, gj1, j1, sacc[nt][1] - m0);
                float t10 = penexp(om1, gi1, pi1, ri1, gj0, j0, sacc[nt][2] - m1);
                float t11 = penexp(om1, gi1, pi1, ri1, gj1, j1, sacc[nt][3] - m1);
                sacc[nt][0] = t00; sacc[nt][1] = t01;
                sacc[nt][2] = t10; sacc[nt][3] = t11;
                rs0 += t00 + t01; rs1 += t10 + t11;
            }
            rs0 += __shfl_xor_sync(0xffffffffu, rs0, 1);
            rs0 += __shfl_xor_sync(0xffffffffu, rs0, 2);
            rs1 += __shfl_xor_sync(0xffffffffu, rs1, 1);
            rs1 += __shfl_xor_sync(0xffffffffu, rs1, 2);
            l0 += rs0; l1 += rs1;

            // --- O += P V ---
            #pragma unroll
            for (int kc = 0; kc < 4; kc++){
                uint32_t af[4];
                af[0] = packh2(sacc[2*kc][0],   sacc[2*kc][1]);
                af[1] = packh2(sacc[2*kc][2],   sacc[2*kc][3]);
                af[2] = packh2(sacc[2*kc+1][0], sacc[2*kc+1][1]);
                af[3] = packh2(sacc[2*kc+1][2], sacc[2*kc+1][3]);
                const int kb = kc*16 + 2*gq;
                #pragma unroll
                for (int dn = 0; dn < 8; dn++){
                    const int d0 = dn*8 + gr;
                    uint32_t bf[2];
                    bf[0] = *(const uint32_t*)&Vs[d0*QSTR + kb];
                    bf[1] = *(const uint32_t*)&Vs[d0*QSTR + kb + 8];
                    mma16(oacc[dn], af, bf);
                }
            }
        }
        __syncthreads();
    }

    // epilogue: scatter to original rows (fp32 output)
    const float inv0 = 1.f / l0, inv1 = 1.f / l1;
    float* op = out + (size_t)b*SS*HH + h*HD;
    #pragma unroll
    for (int dn = 0; dn < 8; dn++){
        const int c0 = dn*8 + 2*gq;
        float2 o0 = { oacc[dn][0]*inv0, oacc[dn][1]*inv0 };
        float2 o1 = { oacc[dn][2]*inv1, oacc[dn][3]*inv1 };
        *(float2*)(op + (size_t)ri0*HH + c0) = o0;
        *(float2*)(op + (size_t)ri1*HH + c0) = o1;
    }
}

// ---------------------------------------------------------------------------
extern "C" void kernel_launch(void* const* d_in, const int* in_sizes, int n_in,
                              void* d_out, int out_size) {
    const float* X  = (const float*)d_in[0];
    const float* Wq = (const float*)d_in[1];
    const float* bq = (const float*)d_in[2];
    const float* Wk = (const float*)d_in[3];
    const float* bk = (const float*)d_in[4];
    const float* Wv = (const float*)d_in[5];
    const float* bv = (const float*)d_in[6];
    const float* Wg = (const float*)d_in[7];
    const float* bg = (const float*)d_in[8];
    float* out = (float*)d_out;

    __half *q, *k, *vt, *x, *w;
    float *g, *p;
    int *perm;
    cudaGetSymbolAddress((void**)&q,  d_q);
    cudaGetSymbolAddress((void**)&k,  d_k);
    cudaGetSymbolAddress((void**)&vt, d_vt);
    cudaGetSymbolAddress((void**)&x,  d_x);
    cudaGetSymbolAddress((void**)&w,  d_w);
    cudaGetSymbolAddress((void**)&g,  d_g);
    cudaGetSymbolAddress((void**)&p,  d_p);
    cudaGetSymbolAddress((void**)&perm, d_perm);

    constexpr int SM_PROJ = NSTG*2*128*PSTR*2;                               // 110592
    constexpr int SM_ATTN = (128*QSTR + 2*JT*QSTR + 2*JT*QSTR)*2 + SS*4;     // 63488
    cudaFuncSetAttribute(gemm_proj,
                         cudaFuncAttributeMaxDynamicSharedMemorySize, SM_PROJ);
    cudaFuncSetAttribute(attn_fused,
                         cudaFuncAttributeMaxDynamicSharedMemorySize, SM_ATTN);

    // merged prep (tconv + gate), then ordering
    prep_kernel<<<3*1024 + BS, 256>>>(Wq, Wk, Wv, w, X, Wg, bg, g, p, x);
    order_kernel<<<BB, 256>>>(p, perm);

    // merged QKV projection (R13 config)
    dim3 gp(HH/128, BS/128, 3);   // (8, 32, 3)
    gemm_proj<<<gp, 256, SM_PROJ>>>(x, w, bq, bk, bv, q, k, vt);

    // non-split attn: bh-fastest grid -> wide itiles launch first
    dim3 ga(BH, SS/128);   // (32, 16)
    attn_fused<<<ga, 256, SM_ATTN>>>(q, k, vt, g, p, perm, out);
}